// round 8
// baseline (speedup 1.0000x reference)
#include <cuda_runtime.h>

#define ROWS 4
#define THREADS 256
#define D 4096

typedef unsigned long long u64;

// H-folded, pre-scaled inner matrices: C[s][n][i][o] = ((B[s][n] @ H64)/64)[i][o]
__device__ float g_C[2 * 64 * 64 * 64];

__device__ __forceinline__ u64 pack2(float x) {
    u64 r; asm("mov.b64 %0,{%1,%1};" : "=l"(r) : "f"(x)); return r;
}
__device__ __forceinline__ void fma2(u64& d, u64 a, u64 b) {
    asm("fma.rn.f32x2 %0,%1,%2,%3;" : "=l"(d) : "l"(a), "l"(b), "l"(d));
}
// bank-conflict-avoiding swizzle: logical (block n, col c) -> physical col
__device__ __forceinline__ int swz(int n, int c) {
    return n * 64 + (c ^ ((n & 7) << 3));
}

// ---------------- prepass: C = (B @ H64) / 64 ----------------
__global__ void prep_kernel(const float* __restrict__ innerB) {
    const int t = blockIdx.x * blockDim.x + threadIdx.x;   // row of a 64x64 block
    const float4* src = reinterpret_cast<const float4*>(innerB + (size_t)t * 64);
    float v[64];
    #pragma unroll
    for (int k = 0; k < 16; k++) {
        float4 f = src[k];
        v[4*k] = f.x; v[4*k+1] = f.y; v[4*k+2] = f.z; v[4*k+3] = f.w;
    }
    #pragma unroll
    for (int h = 1; h < 64; h <<= 1)
        #pragma unroll
        for (int m = 0; m < 64; m += 2*h)
            #pragma unroll
            for (int k = 0; k < h; k++) {
                float a = v[m+k], b = v[m+k+h];
                v[m+k] = a + b; v[m+k+h] = a - b;
            }
    float4* dst = reinterpret_cast<float4*>(g_C + (size_t)t * 64);
    const float s = 1.0f / 64.0f;
    #pragma unroll
    for (int k = 0; k < 16; k++)
        dst[k] = make_float4(v[4*k]*s, v[4*k+1]*s, v[4*k+2]*s, v[4*k+3]*s);
}

// ---------------- main fused kernel (2 CTAs / SM) ----------------
__global__ __launch_bounds__(THREADS, 2)
void bh_fused_kernel(const float* __restrict__ x,
                     const float* __restrict__ finalB,
                     float* __restrict__ out)
{
    extern __shared__ float sd[];   // ROWS * D floats, swizzled layout (64 KB)
    const int tid = threadIdx.x;
    const size_t row0 = (size_t)blockIdx.x * ROWS;

    // ---- load ROWS rows (coalesced gmem read, swizzled smem store) ----
    {
        const float4* gx = reinterpret_cast<const float4*>(x + row0 * D);
        float4* s4 = reinterpret_cast<float4*>(sd);
        #pragma unroll
        for (int k = 0; k < (ROWS * D / 4) / THREADS; k++) {
            const int f   = tid + k * THREADS;
            const int r   = f >> 10;                  // 1024 float4 per row
            const int cq  = f & 1023;
            const int n   = cq >> 4;
            const int c   = (cq & 15) * 4;
            s4[r * 1024 + (swz(n, c) >> 2)] = gx[f];
        }
    }
    __syncthreads();

    const int g  = tid >> 2;         // group 0..63 (4 threads per group)
    const int ob = (tid & 3) * 16;   // output-col base within group (16 cols)
    const int pb0 = swz(g, ob);      // physical base of first 8-col chunk
    const int pb1 = swz(g, ob + 8);  // physical base of second 8-col chunk

    #pragma unroll 1
    for (int stage = 0; stage < 2; stage++) {
        // ---- block-diag 64x64 matmul with C (inner H64 + scale folded) ----
        const float* C = g_C + ((size_t)stage * 64 + g) * 64 * 64;

        u64 acc[ROWS][8];
        #pragma unroll
        for (int r = 0; r < ROWS; r++)
            #pragma unroll
            for (int p = 0; p < 8; p++)
                acc[r][p] = 0ull;

        #pragma unroll 1
        for (int j = 0; j < 64; j += 4) {
            // hoist this j-block's C rows (16 LDG.128 back-to-back)
            ulonglong2 cv[4][4];
            #pragma unroll
            for (int jj = 0; jj < 4; jj++) {
                cv[jj][0] = *reinterpret_cast<const ulonglong2*>(&C[(j + jj) * 64 + ob]);
                cv[jj][1] = *reinterpret_cast<const ulonglong2*>(&C[(j + jj) * 64 + ob + 4]);
                cv[jj][2] = *reinterpret_cast<const ulonglong2*>(&C[(j + jj) * 64 + ob + 8]);
                cv[jj][3] = *reinterpret_cast<const ulonglong2*>(&C[(j + jj) * 64 + ob + 12]);
            }
            const int pj = swz(g, j);
            #pragma unroll
            for (int r = 0; r < ROWS; r++) {
                const float4 xv = *reinterpret_cast<const float4*>(&sd[r * D + pj]);
                u64 xs;
                xs = pack2(xv.x);
                fma2(acc[r][0], xs, cv[0][0].x); fma2(acc[r][1], xs, cv[0][0].y);
                fma2(acc[r][2], xs, cv[0][1].x); fma2(acc[r][3], xs, cv[0][1].y);
                fma2(acc[r][4], xs, cv[0][2].x); fma2(acc[r][5], xs, cv[0][2].y);
                fma2(acc[r][6], xs, cv[0][3].x); fma2(acc[r][7], xs, cv[0][3].y);
                xs = pack2(xv.y);
                fma2(acc[r][0], xs, cv[1][0].x); fma2(acc[r][1], xs, cv[1][0].y);
                fma2(acc[r][2], xs, cv[1][1].x); fma2(acc[r][3], xs, cv[1][1].y);
                fma2(acc[r][4], xs, cv[1][2].x); fma2(acc[r][5], xs, cv[1][2].y);
                fma2(acc[r][6], xs, cv[1][3].x); fma2(acc[r][7], xs, cv[1][3].y);
                xs = pack2(xv.z);
                fma2(acc[r][0], xs, cv[2][0].x); fma2(acc[r][1], xs, cv[2][0].y);
                fma2(acc[r][2], xs, cv[2][1].x); fma2(acc[r][3], xs, cv[2][1].y);
                fma2(acc[r][4], xs, cv[2][2].x); fma2(acc[r][5], xs, cv[2][2].y);
                fma2(acc[r][6], xs, cv[2][3].x); fma2(acc[r][7], xs, cv[2][3].y);
                xs = pack2(xv.w);
                fma2(acc[r][0], xs, cv[3][0].x); fma2(acc[r][1], xs, cv[3][0].y);
                fma2(acc[r][2], xs, cv[3][1].x); fma2(acc[r][3], xs, cv[3][1].y);
                fma2(acc[r][4], xs, cv[3][2].x); fma2(acc[r][5], xs, cv[3][2].y);
                fma2(acc[r][6], xs, cv[3][3].x); fma2(acc[r][7], xs, cv[3][3].y);
            }
        }
        __syncthreads();   // all reads of the stage input done before overwrite
        #pragma unroll
        for (int r = 0; r < ROWS; r++) {
            ulonglong2* sp0 = reinterpret_cast<ulonglong2*>(&sd[r * D + pb0]);
            sp0[0] = make_ulonglong2(acc[r][0], acc[r][1]);
            sp0[1] = make_ulonglong2(acc[r][2], acc[r][3]);
            ulonglong2* sp1 = reinterpret_cast<ulonglong2*>(&sd[r * D + pb1]);
            sp1[0] = make_ulonglong2(acc[r][4], acc[r][5]);
            sp1[1] = make_ulonglong2(acc[r][6], acc[r][7]);
        }
        __syncthreads();

        // ---- outer H64 (stride-64 across blocks), register-resident ----
        {
            const int hr = tid >> 6;      // row 0..3
            const int hj = tid & 63;      // within-block column
            float v[64];
            #pragma unroll
            for (int m = 0; m < 64; m++)
                v[m] = sd[hr * D + m * 64 + (hj ^ ((m & 7) << 3))];
            #pragma unroll
            for (int h = 1; h < 64; h <<= 1)
                #pragma unroll
                for (int m0 = 0; m0 < 64; m0 += 2*h)
                    #pragma unroll
                    for (int k = 0; k < h; k++) {
                        float a = v[m0+k], b = v[m0+k+h];
                        v[m0+k] = a + b; v[m0+k+h] = a - b;
                    }
            #pragma unroll
            for (int m = 0; m < 64; m++)
                sd[hr * D + m * 64 + (hj ^ ((m & 7) << 3))] = v[m];
        }
        __syncthreads();
    }

    // ---------------- final block-diag 128 x (32x32) matmul -> GMEM ----------------
    {
        const int rect = tid >> 1;        // 0..127 (2 threads per rect)
        const int ob2  = (tid & 1) * 16;  // 16 output cols per thread
        const int n    = rect >> 1;
        const int cb   = (rect & 1) * 32;
        const float* B = finalB + (size_t)rect * 32 * 32;

        u64 acc[ROWS][8];
        #pragma unroll
        for (int r = 0; r < ROWS; r++)
            #pragma unroll
            for (int p = 0; p < 8; p++)
                acc[r][p] = 0ull;

        #pragma unroll 1
        for (int j = 0; j < 32; j += 4) {
            ulonglong2 bv[4][4];
            #pragma unroll
            for (int jj = 0; jj < 4; jj++) {
                bv[jj][0] = *reinterpret_cast<const ulonglong2*>(&B[(j + jj) * 32 + ob2]);
                bv[jj][1] = *reinterpret_cast<const ulonglong2*>(&B[(j + jj) * 32 + ob2 + 4]);
                bv[jj][2] = *reinterpret_cast<const ulonglong2*>(&B[(j + jj) * 32 + ob2 + 8]);
                bv[jj][3] = *reinterpret_cast<const ulonglong2*>(&B[(j + jj) * 32 + ob2 + 12]);
            }
            const int pj = swz(n, cb + j);
            #pragma unroll
            for (int r = 0; r < ROWS; r++) {
                const float4 xv = *reinterpret_cast<const float4*>(&sd[r * D + pj]);
                u64 xs;
                xs = pack2(xv.x);
                fma2(acc[r][0], xs, bv[0][0].x); fma2(acc[r][1], xs, bv[0][0].y);
                fma2(acc[r][2], xs, bv[0][1].x); fma2(acc[r][3], xs, bv[0][1].y);
                fma2(acc[r][4], xs, bv[0][2].x); fma2(acc[r][5], xs, bv[0][2].y);
                fma2(acc[r][6], xs, bv[0][3].x); fma2(acc[r][7], xs, bv[0][3].y);
                xs = pack2(xv.y);
                fma2(acc[r][0], xs, bv[1][0].x); fma2(acc[r][1], xs, bv[1][0].y);
                fma2(acc[r][2], xs, bv[1][1].x); fma2(acc[r][3], xs, bv[1][1].y);
                fma2(acc[r][4], xs, bv[1][2].x); fma2(acc[r][5], xs, bv[1][2].y);
                fma2(acc[r][6], xs, bv[1][3].x); fma2(acc[r][7], xs, bv[1][3].y);
                xs = pack2(xv.z);
                fma2(acc[r][0], xs, bv[2][0].x); fma2(acc[r][1], xs, bv[2][0].y);
                fma2(acc[r][2], xs, bv[2][1].x); fma2(acc[r][3], xs, bv[2][1].y);
                fma2(acc[r][4], xs, bv[2][2].x); fma2(acc[r][5], xs, bv[2][2].y);
                fma2(acc[r][6], xs, bv[2][3].x); fma2(acc[r][7], xs, bv[2][3].y);
                xs = pack2(xv.w);
                fma2(acc[r][0], xs, bv[3][0].x); fma2(acc[r][1], xs, bv[3][0].y);
                fma2(acc[r][2], xs, bv[3][1].x); fma2(acc[r][3], xs, bv[3][1].y);
                fma2(acc[r][4], xs, bv[3][2].x); fma2(acc[r][5], xs, bv[3][2].y);
                fma2(acc[r][6], xs, bv[3][3].x); fma2(acc[r][7], xs, bv[3][3].y);
            }
        }
        #pragma unroll
        for (int r = 0; r < ROWS; r++) {
            ulonglong2* op = reinterpret_cast<ulonglong2*>(out + (row0 + r) * D + rect * 32 + ob2);
            op[0] = make_ulonglong2(acc[r][0], acc[r][1]);
            op[1] = make_ulonglong2(acc[r][2], acc[r][3]);
            op[2] = make_ulonglong2(acc[r][4], acc[r][5]);
            op[3] = make_ulonglong2(acc[r][6], acc[r][7]);
        }
    }
}

extern "C" void kernel_launch(void* const* d_in, const int* in_sizes, int n_in,
                              void* d_out, int out_size) {
    const float* x  = (const float*)d_in[0];   // [4,4096,4096] f32
    const float* iB = (const float*)d_in[1];   // [2,64,64,64]  f32
    const float* fB = (const float*)d_in[2];   // [128,32,32]   f32
    float* out = (float*)d_out;                // [4,4096,4096] f32

    prep_kernel<<<64, 128>>>(iB);

    const int smem = ROWS * D * sizeof(float); // 65536 bytes
    cudaFuncSetAttribute(bh_fused_kernel,
                         cudaFuncAttributeMaxDynamicSharedMemorySize, smem);
    const int nrows = 4 * 4096;
    bh_fused_kernel<<<nrows / ROWS, THREADS, smem>>>(x, fB, out);
}

// round 9
// speedup vs baseline: 2.1324x; 2.1324x over previous
#include <cuda_runtime.h>

#define ROWS 8
#define THREADS 512
#define D 4096

typedef unsigned long long u64;

// H-folded, pre-scaled inner matrices: C[s][n] = (B[s][n] @ H64) / 64
__device__ float g_C[2 * 64 * 64 * 64];

__device__ __forceinline__ u64 pack2(float x) {
    u64 r; asm("mov.b64 %0,{%1,%1};" : "=l"(r) : "f"(x)); return r;
}
__device__ __forceinline__ void fma2(u64& d, u64 a, u64 b) {
    asm("fma.rn.f32x2 %0,%1,%2,%3;" : "=l"(d) : "l"(a), "l"(b), "l"(d));
}
// bank-conflict-avoiding swizzle: logical (block n, col c) -> physical col
__device__ __forceinline__ int swz(int n, int c) {
    return n * 64 + (c ^ ((n & 7) << 3));
}

// ---------------- prepass: C = (B @ H64) / 64 ----------------
__global__ void prep_kernel(const float* __restrict__ innerB) {
    const int t = blockIdx.x * blockDim.x + threadIdx.x;   // row of a 64x64 block
    const float4* src = reinterpret_cast<const float4*>(innerB + (size_t)t * 64);
    float v[64];
    #pragma unroll
    for (int k = 0; k < 16; k++) {
        float4 f = src[k];
        v[4*k] = f.x; v[4*k+1] = f.y; v[4*k+2] = f.z; v[4*k+3] = f.w;
    }
    #pragma unroll
    for (int h = 1; h < 64; h <<= 1)
        #pragma unroll
        for (int m = 0; m < 64; m += 2*h)
            #pragma unroll
            for (int k = 0; k < h; k++) {
                float a = v[m+k], b = v[m+k+h];
                v[m+k] = a + b; v[m+k+h] = a - b;
            }
    float4* dst = reinterpret_cast<float4*>(g_C + (size_t)t * 64);
    const float s = 1.0f / 64.0f;
    #pragma unroll
    for (int k = 0; k < 16; k++)
        dst[k] = make_float4(v[4*k]*s, v[4*k+1]*s, v[4*k+2]*s, v[4*k+3]*s);
}

// ---------------- main fused kernel ----------------
__global__ __launch_bounds__(THREADS, 1)
void bh_fused_kernel(const float* __restrict__ x,
                     const float* __restrict__ finalB,
                     float* __restrict__ out)
{
    extern __shared__ float sd[];   // ROWS * D floats, swizzled layout
    const int tid = threadIdx.x;
    const size_t row0 = (size_t)blockIdx.x * ROWS;

    // ---- load ROWS rows (coalesced gmem read, swizzled smem store) ----
    {
        const float4* gx = reinterpret_cast<const float4*>(x + row0 * D);
        float4* s4 = reinterpret_cast<float4*>(sd);
        #pragma unroll
        for (int k = 0; k < (ROWS * D / 4) / THREADS; k++) {
            const int f   = tid + k * THREADS;
            const int r   = f >> 10;                  // 1024 float4 per row
            const int cq  = f & 1023;
            const int n   = cq >> 4;
            const int c   = (cq & 15) * 4;
            s4[r * 1024 + (swz(n, c) >> 2)] = gx[f];
        }
    }
    __syncthreads();

    const int g  = tid >> 3;         // group 0..63 (8 threads per group)
    const int ob = (tid & 7) * 8;    // output-col base within group
    const int pb = swz(g, ob);       // physical col base for writes (8-aligned)

    #pragma unroll 1
    for (int stage = 0; stage < 2; stage++) {
        // ---- block-diag 64x64 matmul with C (inner H64 + scale folded) ----
        const float* C = g_C + ((size_t)stage * 64 + g) * 64 * 64;

        u64 acc[ROWS][4];
        #pragma unroll
        for (int r = 0; r < ROWS; r++)
            #pragma unroll
            for (int p = 0; p < 4; p++)
                acc[r][p] = 0ull;

        #pragma unroll 1
        for (int j = 0; j < 64; j += 4) {
            // hoist this block's C rows (8 LDG.128 back-to-back, MLP=8)
            ulonglong2 c0v[4], c1v[4];
            #pragma unroll
            for (int jj = 0; jj < 4; jj++) {
                c0v[jj] = *reinterpret_cast<const ulonglong2*>(&C[(j + jj) * 64 + ob]);
                c1v[jj] = *reinterpret_cast<const ulonglong2*>(&C[(j + jj) * 64 + ob + 4]);
            }
            const int pj = swz(g, j);
            // JIT x: load next row's x while fma-ing current row
            float4 xv = *reinterpret_cast<const float4*>(&sd[0 * D + pj]);
            #pragma unroll
            for (int r = 0; r < ROWS; r++) {
                float4 xn;
                if (r < ROWS - 1)
                    xn = *reinterpret_cast<const float4*>(&sd[(r + 1) * D + pj]);
                u64 xs;
                xs = pack2(xv.x);
                fma2(acc[r][0], xs, c0v[0].x); fma2(acc[r][1], xs, c0v[0].y);
                fma2(acc[r][2], xs, c1v[0].x); fma2(acc[r][3], xs, c1v[0].y);
                xs = pack2(xv.y);
                fma2(acc[r][0], xs, c0v[1].x); fma2(acc[r][1], xs, c0v[1].y);
                fma2(acc[r][2], xs, c1v[1].x); fma2(acc[r][3], xs, c1v[1].y);
                xs = pack2(xv.z);
                fma2(acc[r][0], xs, c0v[2].x); fma2(acc[r][1], xs, c0v[2].y);
                fma2(acc[r][2], xs, c1v[2].x); fma2(acc[r][3], xs, c1v[2].y);
                xs = pack2(xv.w);
                fma2(acc[r][0], xs, c0v[3].x); fma2(acc[r][1], xs, c0v[3].y);
                fma2(acc[r][2], xs, c1v[3].x); fma2(acc[r][3], xs, c1v[3].y);
                xv = xn;
            }
        }
        // block g's region is read/written only by its own group (one warp):
        // warp-scope ordering suffices before the in-place overwrite.
        __syncwarp();
        #pragma unroll
        for (int r = 0; r < ROWS; r++) {
            ulonglong2* sp = reinterpret_cast<ulonglong2*>(&sd[r * D + pb]);
            sp[0] = make_ulonglong2(acc[r][0], acc[r][1]);
            sp[1] = make_ulonglong2(acc[r][2], acc[r][3]);
        }
        __syncthreads();

        // ---- outer H64 (stride-64 across blocks), register-resident ----
        {
            const int hr = tid >> 6;      // row 0..7
            const int hj = tid & 63;      // within-block column
            float v[64];
            #pragma unroll
            for (int m = 0; m < 64; m++)
                v[m] = sd[hr * D + m * 64 + (hj ^ ((m & 7) << 3))];
            #pragma unroll
            for (int h = 1; h < 64; h <<= 1)
                #pragma unroll
                for (int m0 = 0; m0 < 64; m0 += 2*h)
                    #pragma unroll
                    for (int k = 0; k < h; k++) {
                        float a = v[m0+k], b = v[m0+k+h];
                        v[m0+k] = a + b; v[m0+k+h] = a - b;
                    }
            #pragma unroll
            for (int m = 0; m < 64; m++)
                sd[hr * D + m * 64 + (hj ^ ((m & 7) << 3))] = v[m];
        }
        __syncthreads();
    }

    // ---------------- final block-diag 128 x (32x32) matmul -> GMEM ----------------
    {
        const int rect = tid >> 2;        // 0..127 (4 threads per rect)
        const int ob2  = (tid & 3) * 8;
        const int n    = rect >> 1;
        const int cb   = (rect & 1) * 32;
        const float* B = finalB + (size_t)rect * 32 * 32;

        u64 acc[ROWS][4];
        #pragma unroll
        for (int r = 0; r < ROWS; r++)
            #pragma unroll
            for (int p = 0; p < 4; p++)
                acc[r][p] = 0ull;

        #pragma unroll 1
        for (int j = 0; j < 32; j += 4) {
            ulonglong2 b0v[4], b1v[4];
            #pragma unroll
            for (int jj = 0; jj < 4; jj++) {
                b0v[jj] = *reinterpret_cast<const ulonglong2*>(&B[(j + jj) * 32 + ob2]);
                b1v[jj] = *reinterpret_cast<const ulonglong2*>(&B[(j + jj) * 32 + ob2 + 4]);
            }
            const int pj = swz(n, cb + j);
            float4 xv = *reinterpret_cast<const float4*>(&sd[0 * D + pj]);
            #pragma unroll
            for (int r = 0; r < ROWS; r++) {
                float4 xn;
                if (r < ROWS - 1)
                    xn = *reinterpret_cast<const float4*>(&sd[(r + 1) * D + pj]);
                u64 xs;
                xs = pack2(xv.x);
                fma2(acc[r][0], xs, b0v[0].x); fma2(acc[r][1], xs, b0v[0].y);
                fma2(acc[r][2], xs, b1v[0].x); fma2(acc[r][3], xs, b1v[0].y);
                xs = pack2(xv.y);
                fma2(acc[r][0], xs, b0v[1].x); fma2(acc[r][1], xs, b0v[1].y);
                fma2(acc[r][2], xs, b1v[1].x); fma2(acc[r][3], xs, b1v[1].y);
                xs = pack2(xv.z);
                fma2(acc[r][0], xs, b0v[2].x); fma2(acc[r][1], xs, b0v[2].y);
                fma2(acc[r][2], xs, b1v[2].x); fma2(acc[r][3], xs, b1v[2].y);
                xs = pack2(xv.w);
                fma2(acc[r][0], xs, b0v[3].x); fma2(acc[r][1], xs, b0v[3].y);
                fma2(acc[r][2], xs, b1v[3].x); fma2(acc[r][3], xs, b1v[3].y);
                xv = xn;
            }
        }
        #pragma unroll
        for (int r = 0; r < ROWS; r++) {
            ulonglong2* op = reinterpret_cast<ulonglong2*>(out + (row0 + r) * D + rect * 32 + ob2);
            op[0] = make_ulonglong2(acc[r][0], acc[r][1]);
            op[1] = make_ulonglong2(acc[r][2], acc[r][3]);
        }
    }
}

extern "C" void kernel_launch(void* const* d_in, const int* in_sizes, int n_in,
                              void* d_out, int out_size) {
    const float* x  = (const float*)d_in[0];   // [4,4096,4096] f32
    const float* iB = (const float*)d_in[1];   // [2,64,64,64]  f32
    const float* fB = (const float*)d_in[2];   // [128,32,32]   f32
    float* out = (float*)d_out;                // [4,4096,4096] f32

    prep_kernel<<<64, 128>>>(iB);

    const int smem = ROWS * D * sizeof(float); // 131072 bytes
    cudaFuncSetAttribute(bh_fused_kernel,
                         cudaFuncAttributeMaxDynamicSharedMemorySize, smem);
    const int nrows = 4 * 4096;
    bh_fused_kernel<<<nrows / ROWS, THREADS, smem>>>(x, fB, out);
}